// round 16
// baseline (speedup 1.0000x reference)
#include <cuda_runtime.h>
#include <cuda_bf16.h>

#define B_    32
#define PRE_  2048
#define POST_ 2048
#define KSPL  32

typedef unsigned int u32;

// ---- static device scratch ---------------------------------------------------
__device__ float g_part[KSPL * B_ * POST_];   // fwd split-K partials (8 MB)
__device__ u32   g_mask[POST_];               // spike bitmask per p (bit b)

// ---- helpers -----------------------------------------------------------------
__device__ __forceinline__ u32 smem_u32(const void* p) {
    u32 a;
    asm("{ .reg .u64 t; cvta.to.shared.u64 t, %1; cvt.u32.u64 %0, t; }" : "=r"(a) : "l"(p));
    return a;
}
__device__ __forceinline__ void mma16816(float* d, const u32* a, u32 b0, u32 b1) {
    asm volatile(
        "mma.sync.aligned.m16n8k16.row.col.f32.bf16.bf16.f32 "
        "{%0,%1,%2,%3}, {%4,%5,%6,%7}, {%8,%9}, {%0,%1,%2,%3};"
        : "+f"(d[0]), "+f"(d[1]), "+f"(d[2]), "+f"(d[3])
        : "r"(a[0]), "r"(a[1]), "r"(a[2]), "r"(a[3]), "r"(b0), "r"(b1));
}
__device__ __forceinline__ void mma1688tf32(float* d, const u32* a, u32 b0, u32 b1) {
    asm volatile(
        "mma.sync.aligned.m16n8k8.row.col.f32.tf32.tf32.f32 "
        "{%0,%1,%2,%3}, {%4,%5,%6,%7}, {%8,%9}, {%0,%1,%2,%3};"
        : "+f"(d[0]), "+f"(d[1]), "+f"(d[2]), "+f"(d[3])
        : "r"(a[0]), "r"(a[1]), "r"(a[2]), "r"(a[3]), "r"(b0), "r"(b1));
}
__device__ __forceinline__ u32 cvt_tf32(float v) {
    u32 r;
    asm("cvt.rna.tf32.f32 %0, %1;" : "=r"(r) : "f"(v));
    return r;
}
#define CP_ASYNC16(dst, src) \
    asm volatile("cp.async.cg.shared.global [%0], [%1], 16;" :: "r"(dst), "l"(src) : "memory")
#define CP_COMMIT()  asm volatile("cp.async.commit_group;" ::: "memory")
#define CP_WAIT(n)   asm volatile("cp.async.wait_group %0;" :: "n"(n) : "memory")

// =============================================================================
// kA: forward split-K partials of i = x @ W^T via tf32 HMMA, 2-split W in regs.
// (unchanged from R15 — best measured variant, 9.8 us)
// =============================================================================
#define KA_RAWS 36
#define KA_XSS  68

__global__ __launch_bounds__(128, 8) void kA(const float* __restrict__ x,
                                             const float* __restrict__ W) {
    __shared__ float raw[2][64 * KA_RAWS];
    __shared__ u32   xs[32 * KA_XSS];

    const int tid = threadIdx.x, wid = tid >> 5, lane = tid & 31;
    const int gid = lane >> 2, tig = lane & 3;
    const int p0 = blockIdx.x * 64;
    const int k0 = blockIdx.y * 64;
    const u32 rawb = smem_u32(&raw[0][0]);

#pragma unroll
    for (int c = 0; c < 2; ++c) {
        const int kb = k0 + c * 32;
#pragma unroll
        for (int i = 0; i < 4; ++i) {
            int u = tid + i * 128;
            int row = u >> 3, g = u & 7;
            CP_ASYNC16(rawb + (u32)(c * 64 * KA_RAWS + row * KA_RAWS + g * 4) * 4,
                       W + (size_t)(p0 + row) * PRE_ + kb + g * 4);
        }
        CP_COMMIT();
    }

    {
        const int b = tid >> 2, kseg = (tid & 3) * 16;
        const float4* xr = reinterpret_cast<const float4*>(x + b * PRE_ + k0 + kseg);
#pragma unroll
        for (int j = 0; j < 4; ++j) {
            float4 v = xr[j];
            xs[b * KA_XSS + kseg + j * 4 + 0] = cvt_tf32(v.x);
            xs[b * KA_XSS + kseg + j * 4 + 1] = cvt_tf32(v.y);
            xs[b * KA_XSS + kseg + j * 4 + 2] = cvt_tf32(v.z);
            xs[b * KA_XSS + kseg + j * 4 + 3] = cvt_tf32(v.w);
        }
    }

    float acc[2][2][4];
#pragma unroll
    for (int i = 0; i < 2; ++i)
#pragma unroll
        for (int j = 0; j < 2; ++j)
#pragma unroll
            for (int r = 0; r < 4; ++r) acc[i][j][r] = 0.0f;

#pragma unroll
    for (int c = 0; c < 2; ++c) {
        if (c == 0) { CP_WAIT(1); } else { CP_WAIT(0); }
        __syncthreads();
        const float* rb = &raw[c][0];
#pragma unroll
        for (int ks = 0; ks < 4; ++ks) {
            const int kc = ks * 8;
            const int kx = c * 32 + kc;
            u32 a[2][4];
#pragma unroll
            for (int mf = 0; mf < 2; ++mf) {
                const int r0 = mf * 16 + gid;
                a[mf][0] = xs[r0 * KA_XSS + kx + tig];
                a[mf][1] = xs[(r0 + 8) * KA_XSS + kx + tig];
                a[mf][2] = xs[r0 * KA_XSS + kx + tig + 4];
                a[mf][3] = xs[(r0 + 8) * KA_XSS + kx + tig + 4];
            }
#pragma unroll
            for (int nf = 0; nf < 2; ++nf) {
                const int n = wid * 16 + nf * 8 + gid;
                float w0 = rb[n * KA_RAWS + kc + tig];
                float w1 = rb[n * KA_RAWS + kc + tig + 4];
                u32 h0 = cvt_tf32(w0), h1 = cvt_tf32(w1);
                u32 l0 = cvt_tf32(w0 - __uint_as_float(h0));
                u32 l1 = cvt_tf32(w1 - __uint_as_float(h1));
                mma1688tf32(acc[0][nf], a[0], h0, h1);
                mma1688tf32(acc[1][nf], a[1], h0, h1);
                mma1688tf32(acc[0][nf], a[0], l0, l1);
                mma1688tf32(acc[1][nf], a[1], l0, l1);
            }
        }
    }

    float* pp = g_part + (size_t)blockIdx.y * (B_ * POST_);
#pragma unroll
    for (int mf = 0; mf < 2; ++mf)
#pragma unroll
        for (int nf = 0; nf < 2; ++nf) {
            const int p = p0 + wid * 16 + nf * 8 + tig * 2;
            const int b = mf * 16 + gid;
            *reinterpret_cast<float2*>(&pp[(size_t)b * POST_ + p]) =
                make_float2(acc[mf][nf][0], acc[mf][nf][1]);
            *reinterpret_cast<float2*>(&pp[(size_t)(b + 8) * POST_ + p]) =
                make_float2(acc[mf][nf][2], acc[mf][nf][3]);
        }
}

// =============================================================================
// kB: reduce split-K partials -> spike output + per-p spike bitmask.
// grid 16 x 256 thr; block handles 128 p columns x all 32 b.
// =============================================================================
__global__ __launch_bounds__(256) void kB(float* __restrict__ out_spike) {
    __shared__ float sps[32][132];
    const int tid = threadIdx.x;
    const int p0 = blockIdx.x * 128;

#pragma unroll
    for (int i = 0; i < 16; ++i) {
        int u = tid + i * 256;
        int b = u >> 7, pl = u & 127;
        int gi = b * POST_ + p0 + pl;
        float s = 0.0f;
#pragma unroll
        for (int k = 0; k < KSPL; ++k) s += g_part[(size_t)k * (B_ * POST_) + gi];
        float spike = (s >= 1.0f) ? 1.0f : 0.0f;
        out_spike[gi] = spike;
        sps[b][pl] = spike;
    }
    __syncthreads();
    if (tid < 128) {
        u32 m = 0;
#pragma unroll
        for (int b = 0; b < 32; ++b)
            if (sps[b][tid] != 0.0f) m |= (1u << b);
        g_mask[p0 + tid] = m;
    }
}

// =============================================================================
// kC: dw = clip(W) * ( -0.5*tpost^T x  +  0.5*spike^T tpre )
//  - dense part: K=32 bf16 HMMA, two passes (tpost hi/lo splits), B tile (x)
//    reused across passes; operands converted in-kernel from raw inputs.
//  - sparse part: spike bitmasks + exact fp32 tpre accumulation in epilogue
//    (E[set bits per p] ~ 0.4).
// grid (16,16) = 256 CTAs (single wave at 2/SM), 256 thr, warps 2(p) x 4(q).
// =============================================================================
#define KC_AS 34       // A/B tile stride (bf16): 17 u32 banks, conflict-free

__global__ __launch_bounds__(256, 2) void kC(const float* __restrict__ x,
                                             const float* __restrict__ W,
                                             const float* __restrict__ tpre,
                                             const float* __restrict__ tpost,
                                             float* __restrict__ dw) {
    __shared__ __nv_bfloat16 As[2][128][KC_AS];  // [-0.5*tpost hi/lo][p][b]
    __shared__ __nv_bfloat16 Bs[128][KC_AS];     // x[q][b]
    __shared__ float         tps[32][132];       // tpre[b][q_local]
    __shared__ u32           msk[128];           // spike mask per p

    const int tid = threadIdx.x, wid = tid >> 5, lane = tid & 31;
    const int gid = lane >> 2, tig = lane & 3;
    const int pw = wid >> 2, qw = wid & 3;
    const int p0 = blockIdx.x * 128, q0 = blockIdx.y * 128;

    // stage: tpost -> As (scaled -0.5, hi/lo), x -> Bs, tpre -> tps, masks
#pragma unroll
    for (int i = 0; i < 16; ++i) {
        int u = tid + i * 256;
        int b = u >> 7, rl = u & 127;
        float v = -0.5f * tpost[b * POST_ + p0 + rl];
        __nv_bfloat16 h = __float2bfloat16(v);
        As[0][rl][b] = h;
        As[1][rl][b] = __float2bfloat16(v - __bfloat162float(h));
        Bs[rl][b]    = __float2bfloat16(x[b * PRE_ + q0 + rl]);
        tps[b][rl]   = tpre[b * PRE_ + q0 + rl];
    }
    if (tid < 128) msk[tid] = g_mask[p0 + tid];
    __syncthreads();

    float acc[4][4][4];   // [mf][nf][reg]
#pragma unroll
    for (int i = 0; i < 4; ++i)
#pragma unroll
        for (int j = 0; j < 4; ++j)
#pragma unroll
            for (int r = 0; r < 4; ++r) acc[i][j][r] = 0.0f;

    // dense part: 2 split passes x 2 k16 steps over b
#pragma unroll
    for (int h = 0; h < 2; ++h)
#pragma unroll
        for (int ks = 0; ks < 2; ++ks) {
            const int kc = ks * 16 + tig * 2;
            u32 a[4][4];
#pragma unroll
            for (int mf = 0; mf < 4; ++mf) {
                const int r0 = pw * 64 + mf * 16 + gid;
                a[mf][0] = *reinterpret_cast<const u32*>(&As[h][r0][kc]);
                a[mf][1] = *reinterpret_cast<const u32*>(&As[h][r0 + 8][kc]);
                a[mf][2] = *reinterpret_cast<const u32*>(&As[h][r0][kc + 8]);
                a[mf][3] = *reinterpret_cast<const u32*>(&As[h][r0 + 8][kc + 8]);
            }
#pragma unroll
            for (int nf = 0; nf < 4; ++nf) {
                const int n = qw * 32 + nf * 8 + gid;
                u32 b0 = *reinterpret_cast<const u32*>(&Bs[n][kc]);
                u32 b1 = *reinterpret_cast<const u32*>(&Bs[n][kc + 8]);
#pragma unroll
                for (int mf = 0; mf < 4; ++mf) mma16816(acc[mf][nf], a[mf], b0, b1);
            }
        }

    // epilogue: sparse exact term1 + clip(W) scale + store
#pragma unroll
    for (int mf = 0; mf < 4; ++mf) {
        const int pla = pw * 64 + mf * 16 + gid;       // local p (row a)
        const int plb = pla + 8;                       // local p (row b)
        u32 m0 = msk[pla], m1 = msk[plb];
        float t0[4][2], t1[4][2];
#pragma unroll
        for (int nf = 0; nf < 4; ++nf) {
            t0[nf][0] = 0.f; t0[nf][1] = 0.f;
            t1[nf][0] = 0.f; t1[nf][1] = 0.f;
        }
        while (m0) {
            int b = __ffs(m0) - 1; m0 &= m0 - 1;
#pragma unroll
            for (int nf = 0; nf < 4; ++nf) {
                const int ql = qw * 32 + nf * 8 + tig * 2;
                t0[nf][0] += tps[b][ql];
                t0[nf][1] += tps[b][ql + 1];
            }
        }
        while (m1) {
            int b = __ffs(m1) - 1; m1 &= m1 - 1;
#pragma unroll
            for (int nf = 0; nf < 4; ++nf) {
                const int ql = qw * 32 + nf * 8 + tig * 2;
                t1[nf][0] += tps[b][ql];
                t1[nf][1] += tps[b][ql + 1];
            }
        }
#pragma unroll
        for (int nf = 0; nf < 4; ++nf) {
            const int p = p0 + pla;
            const int q = q0 + qw * 32 + nf * 8 + tig * 2;
            float2 w0 = *reinterpret_cast<const float2*>(&W[(size_t)p * PRE_ + q]);
            float2 w1 = *reinterpret_cast<const float2*>(&W[(size_t)(p + 8) * PRE_ + q]);
            float2 o0, o1;
            o0.x = fminf(fmaxf(w0.x, -1.f), 1.f) * (acc[mf][nf][0] + 0.5f * t0[nf][0]);
            o0.y = fminf(fmaxf(w0.y, -1.f), 1.f) * (acc[mf][nf][1] + 0.5f * t0[nf][1]);
            o1.x = fminf(fmaxf(w1.x, -1.f), 1.f) * (acc[mf][nf][2] + 0.5f * t1[nf][0]);
            o1.y = fminf(fmaxf(w1.y, -1.f), 1.f) * (acc[mf][nf][3] + 0.5f * t1[nf][1]);
            *reinterpret_cast<float2*>(&dw[(size_t)p * PRE_ + q])       = o0;
            *reinterpret_cast<float2*>(&dw[(size_t)(p + 8) * PRE_ + q]) = o1;
        }
    }
}

// =============================================================================
extern "C" void kernel_launch(void* const* d_in, const int* in_sizes, int n_in,
                              void* d_out, int out_size) {
    const float* x     = (const float*)d_in[0];   // [32, 2048]
    const float* W     = (const float*)d_in[1];   // [2048, 2048]
    const float* tpre  = (const float*)d_in[2];   // [32, 2048]
    const float* tpost = (const float*)d_in[3];   // [32, 2048]
    float* out     = (float*)d_out;
    float* spike_o = out;                         // [32, 2048]
    float* dw_o    = out + B_ * POST_;            // [2048, 2048]

    kA<<<dim3(POST_ / 64, KSPL), 128>>>(x, W);
    kB<<<POST_ / 128, 256>>>(spike_o);
    kC<<<dim3(POST_ / 128, PRE_ / 128), 256>>>(x, W, tpre, tpost, dw_o);
}

// round 17
// speedup vs baseline: 1.3839x; 1.3839x over previous
#include <cuda_runtime.h>
#include <cuda_bf16.h>

#define B_    32
#define PRE_  2048
#define POST_ 2048
#define KSPL  32

typedef unsigned int u32;

// ---- static device scratch ---------------------------------------------------
__device__ float g_part[KSPL * B_ * POST_];   // fwd split-K partials (8 MB)
__device__ u32   g_mask[POST_];               // spike bitmask per p (bit b)

// ---- helpers -----------------------------------------------------------------
__device__ __forceinline__ u32 smem_u32(const void* p) {
    u32 a;
    asm("{ .reg .u64 t; cvta.to.shared.u64 t, %1; cvt.u32.u64 %0, t; }" : "=r"(a) : "l"(p));
    return a;
}
__device__ __forceinline__ void mma16816(float* d, const u32* a, u32 b0, u32 b1) {
    asm volatile(
        "mma.sync.aligned.m16n8k16.row.col.f32.bf16.bf16.f32 "
        "{%0,%1,%2,%3}, {%4,%5,%6,%7}, {%8,%9}, {%0,%1,%2,%3};"
        : "+f"(d[0]), "+f"(d[1]), "+f"(d[2]), "+f"(d[3])
        : "r"(a[0]), "r"(a[1]), "r"(a[2]), "r"(a[3]), "r"(b0), "r"(b1));
}
__device__ __forceinline__ void mma1688tf32(float* d, const u32* a, u32 b0, u32 b1) {
    asm volatile(
        "mma.sync.aligned.m16n8k8.row.col.f32.tf32.tf32.f32 "
        "{%0,%1,%2,%3}, {%4,%5,%6,%7}, {%8,%9}, {%0,%1,%2,%3};"
        : "+f"(d[0]), "+f"(d[1]), "+f"(d[2]), "+f"(d[3])
        : "r"(a[0]), "r"(a[1]), "r"(a[2]), "r"(a[3]), "r"(b0), "r"(b1));
}
__device__ __forceinline__ u32 cvt_tf32(float v) {
    u32 r;
    asm("cvt.rna.tf32.f32 %0, %1;" : "=r"(r) : "f"(v));
    return r;
}
#define CP_ASYNC16(dst, src) \
    asm volatile("cp.async.cg.shared.global [%0], [%1], 16;" :: "r"(dst), "l"(src) : "memory")
#define CP_COMMIT()  asm volatile("cp.async.commit_group;" ::: "memory")
#define CP_WAIT(n)   asm volatile("cp.async.wait_group %0;" :: "n"(n) : "memory")

// =============================================================================
// kA: forward split-K partials of i = x @ W^T via tf32 HMMA, 2-split W in regs.
// (unchanged — best measured variant, 9.8 us)
// =============================================================================
#define KA_RAWS 36
#define KA_XSS  68

__global__ __launch_bounds__(128, 8) void kA(const float* __restrict__ x,
                                             const float* __restrict__ W) {
    __shared__ float raw[2][64 * KA_RAWS];
    __shared__ u32   xs[32 * KA_XSS];

    const int tid = threadIdx.x, wid = tid >> 5, lane = tid & 31;
    const int gid = lane >> 2, tig = lane & 3;
    const int p0 = blockIdx.x * 64;
    const int k0 = blockIdx.y * 64;
    const u32 rawb = smem_u32(&raw[0][0]);

#pragma unroll
    for (int c = 0; c < 2; ++c) {
        const int kb = k0 + c * 32;
#pragma unroll
        for (int i = 0; i < 4; ++i) {
            int u = tid + i * 128;
            int row = u >> 3, g = u & 7;
            CP_ASYNC16(rawb + (u32)(c * 64 * KA_RAWS + row * KA_RAWS + g * 4) * 4,
                       W + (size_t)(p0 + row) * PRE_ + kb + g * 4);
        }
        CP_COMMIT();
    }

    {
        const int b = tid >> 2, kseg = (tid & 3) * 16;
        const float4* xr = reinterpret_cast<const float4*>(x + b * PRE_ + k0 + kseg);
#pragma unroll
        for (int j = 0; j < 4; ++j) {
            float4 v = xr[j];
            xs[b * KA_XSS + kseg + j * 4 + 0] = cvt_tf32(v.x);
            xs[b * KA_XSS + kseg + j * 4 + 1] = cvt_tf32(v.y);
            xs[b * KA_XSS + kseg + j * 4 + 2] = cvt_tf32(v.z);
            xs[b * KA_XSS + kseg + j * 4 + 3] = cvt_tf32(v.w);
        }
    }

    float acc[2][2][4];
#pragma unroll
    for (int i = 0; i < 2; ++i)
#pragma unroll
        for (int j = 0; j < 2; ++j)
#pragma unroll
            for (int r = 0; r < 4; ++r) acc[i][j][r] = 0.0f;

#pragma unroll
    for (int c = 0; c < 2; ++c) {
        if (c == 0) { CP_WAIT(1); } else { CP_WAIT(0); }
        __syncthreads();
        const float* rb = &raw[c][0];
#pragma unroll
        for (int ks = 0; ks < 4; ++ks) {
            const int kc = ks * 8;
            const int kx = c * 32 + kc;
            u32 a[2][4];
#pragma unroll
            for (int mf = 0; mf < 2; ++mf) {
                const int r0 = mf * 16 + gid;
                a[mf][0] = xs[r0 * KA_XSS + kx + tig];
                a[mf][1] = xs[(r0 + 8) * KA_XSS + kx + tig];
                a[mf][2] = xs[r0 * KA_XSS + kx + tig + 4];
                a[mf][3] = xs[(r0 + 8) * KA_XSS + kx + tig + 4];
            }
#pragma unroll
            for (int nf = 0; nf < 2; ++nf) {
                const int n = wid * 16 + nf * 8 + gid;
                float w0 = rb[n * KA_RAWS + kc + tig];
                float w1 = rb[n * KA_RAWS + kc + tig + 4];
                u32 h0 = cvt_tf32(w0), h1 = cvt_tf32(w1);
                u32 l0 = cvt_tf32(w0 - __uint_as_float(h0));
                u32 l1 = cvt_tf32(w1 - __uint_as_float(h1));
                mma1688tf32(acc[0][nf], a[0], h0, h1);
                mma1688tf32(acc[1][nf], a[1], h0, h1);
                mma1688tf32(acc[0][nf], a[0], l0, l1);
                mma1688tf32(acc[1][nf], a[1], l0, l1);
            }
        }
    }

    float* pp = g_part + (size_t)blockIdx.y * (B_ * POST_);
#pragma unroll
    for (int mf = 0; mf < 2; ++mf)
#pragma unroll
        for (int nf = 0; nf < 2; ++nf) {
            const int p = p0 + wid * 16 + nf * 8 + tig * 2;
            const int b = mf * 16 + gid;
            *reinterpret_cast<float2*>(&pp[(size_t)b * POST_ + p]) =
                make_float2(acc[mf][nf][0], acc[mf][nf][1]);
            *reinterpret_cast<float2*>(&pp[(size_t)(b + 8) * POST_ + p]) =
                make_float2(acc[mf][nf][2], acc[mf][nf][3]);
        }
}

// =============================================================================
// kB: reduce split-K partials -> spike output + per-p spike bitmask.
// grid 64 x 256 thr (proven R12-R15 shape): 32 p-columns/block, 4 elem/thread,
// 128B-coalesced partial reads. Mask built from smem by 32 threads/block.
// =============================================================================
__global__ __launch_bounds__(256) void kB(float* __restrict__ out_spike) {
    __shared__ float sps[32][36];
    const int tid = threadIdx.x;
    const int c0 = blockIdx.x * 32;

#pragma unroll
    for (int r = 0; r < 4; ++r) {
        int u = tid + r * 256;
        int b = u >> 5, j = u & 31;
        int gi = b * POST_ + c0 + j;
        float s = 0.0f;
#pragma unroll
        for (int k = 0; k < KSPL; ++k) s += g_part[(size_t)k * (B_ * POST_) + gi];
        float spike = (s >= 1.0f) ? 1.0f : 0.0f;
        out_spike[gi] = spike;
        sps[b][j] = spike;
    }
    __syncthreads();
    if (tid < 32) {
        u32 m = 0;
#pragma unroll
        for (int b = 0; b < 32; ++b)
            if (sps[b][tid] != 0.0f) m |= (1u << b);
        g_mask[c0 + tid] = m;
    }
}

// =============================================================================
// kC: dw = clip(W) * ( -0.5*tpost^T x  +  0.5*spike^T tpre )
//  - dense part: K=32 bf16 HMMA, two passes (tpost hi/lo splits).
//  - sparse part: spike bitmasks + exact fp32 tpre accumulation in epilogue.
// grid (16,16) = 256 CTAs, 256 thr, warps 2(p) x 4(q).
// =============================================================================
#define KC_AS 34       // A/B tile stride (bf16)

__global__ __launch_bounds__(256, 2) void kC(const float* __restrict__ x,
                                             const float* __restrict__ W,
                                             const float* __restrict__ tpre,
                                             const float* __restrict__ tpost,
                                             float* __restrict__ dw) {
    __shared__ __nv_bfloat16 As[2][128][KC_AS];  // [-0.5*tpost hi/lo][p][b]
    __shared__ __nv_bfloat16 Bs[128][KC_AS];     // x[q][b]
    __shared__ float         tps[32][132];       // tpre[b][q_local]
    __shared__ u32           msk[128];           // spike mask per p

    const int tid = threadIdx.x, wid = tid >> 5, lane = tid & 31;
    const int gid = lane >> 2, tig = lane & 3;
    const int pw = wid >> 2, qw = wid & 3;
    const int p0 = blockIdx.x * 128, q0 = blockIdx.y * 128;

#pragma unroll
    for (int i = 0; i < 16; ++i) {
        int u = tid + i * 256;
        int b = u >> 7, rl = u & 127;
        float v = -0.5f * tpost[b * POST_ + p0 + rl];
        __nv_bfloat16 h = __float2bfloat16(v);
        As[0][rl][b] = h;
        As[1][rl][b] = __float2bfloat16(v - __bfloat162float(h));
        Bs[rl][b]    = __float2bfloat16(x[b * PRE_ + q0 + rl]);
        tps[b][rl]   = tpre[b * PRE_ + q0 + rl];
    }
    if (tid < 128) msk[tid] = g_mask[p0 + tid];
    __syncthreads();

    float acc[4][4][4];
#pragma unroll
    for (int i = 0; i < 4; ++i)
#pragma unroll
        for (int j = 0; j < 4; ++j)
#pragma unroll
            for (int r = 0; r < 4; ++r) acc[i][j][r] = 0.0f;

#pragma unroll
    for (int h = 0; h < 2; ++h)
#pragma unroll
        for (int ks = 0; ks < 2; ++ks) {
            const int kc = ks * 16 + tig * 2;
            u32 a[4][4];
#pragma unroll
            for (int mf = 0; mf < 4; ++mf) {
                const int r0 = pw * 64 + mf * 16 + gid;
                a[mf][0] = *reinterpret_cast<const u32*>(&As[h][r0][kc]);
                a[mf][1] = *reinterpret_cast<const u32*>(&As[h][r0 + 8][kc]);
                a[mf][2] = *reinterpret_cast<const u32*>(&As[h][r0][kc + 8]);
                a[mf][3] = *reinterpret_cast<const u32*>(&As[h][r0 + 8][kc + 8]);
            }
#pragma unroll
            for (int nf = 0; nf < 4; ++nf) {
                const int n = qw * 32 + nf * 8 + gid;
                u32 b0 = *reinterpret_cast<const u32*>(&Bs[n][kc]);
                u32 b1 = *reinterpret_cast<const u32*>(&Bs[n][kc + 8]);
#pragma unroll
                for (int mf = 0; mf < 4; ++mf) mma16816(acc[mf][nf], a[mf], b0, b1);
            }
        }

#pragma unroll
    for (int mf = 0; mf < 4; ++mf) {
        const int pla = pw * 64 + mf * 16 + gid;
        const int plb = pla + 8;
        u32 m0 = msk[pla], m1 = msk[plb];
        float t0[4][2], t1[4][2];
#pragma unroll
        for (int nf = 0; nf < 4; ++nf) {
            t0[nf][0] = 0.f; t0[nf][1] = 0.f;
            t1[nf][0] = 0.f; t1[nf][1] = 0.f;
        }
        while (m0) {
            int b = __ffs(m0) - 1; m0 &= m0 - 1;
#pragma unroll
            for (int nf = 0; nf < 4; ++nf) {
                const int ql = qw * 32 + nf * 8 + tig * 2;
                t0[nf][0] += tps[b][ql];
                t0[nf][1] += tps[b][ql + 1];
            }
        }
        while (m1) {
            int b = __ffs(m1) - 1; m1 &= m1 - 1;
#pragma unroll
            for (int nf = 0; nf < 4; ++nf) {
                const int ql = qw * 32 + nf * 8 + tig * 2;
                t1[nf][0] += tps[b][ql];
                t1[nf][1] += tps[b][ql + 1];
            }
        }
#pragma unroll
        for (int nf = 0; nf < 4; ++nf) {
            const int p = p0 + pla;
            const int q = q0 + qw * 32 + nf * 8 + tig * 2;
            float2 w0 = *reinterpret_cast<const float2*>(&W[(size_t)p * PRE_ + q]);
            float2 w1 = *reinterpret_cast<const float2*>(&W[(size_t)(p + 8) * PRE_ + q]);
            float2 o0, o1;
            o0.x = fminf(fmaxf(w0.x, -1.f), 1.f) * (acc[mf][nf][0] + 0.5f * t0[nf][0]);
            o0.y = fminf(fmaxf(w0.y, -1.f), 1.f) * (acc[mf][nf][1] + 0.5f * t0[nf][1]);
            o1.x = fminf(fmaxf(w1.x, -1.f), 1.f) * (acc[mf][nf][2] + 0.5f * t1[nf][0]);
            o1.y = fminf(fmaxf(w1.y, -1.f), 1.f) * (acc[mf][nf][3] + 0.5f * t1[nf][1]);
            *reinterpret_cast<float2*>(&dw[(size_t)p * PRE_ + q])       = o0;
            *reinterpret_cast<float2*>(&dw[(size_t)(p + 8) * PRE_ + q]) = o1;
        }
    }
}

// =============================================================================
extern "C" void kernel_launch(void* const* d_in, const int* in_sizes, int n_in,
                              void* d_out, int out_size) {
    const float* x     = (const float*)d_in[0];   // [32, 2048]
    const float* W     = (const float*)d_in[1];   // [2048, 2048]
    const float* tpre  = (const float*)d_in[2];   // [32, 2048]
    const float* tpost = (const float*)d_in[3];   // [32, 2048]
    float* out     = (float*)d_out;
    float* spike_o = out;                         // [32, 2048]
    float* dw_o    = out + B_ * POST_;            // [2048, 2048]

    kA<<<dim3(POST_ / 64, KSPL), 128>>>(x, W);
    kB<<<64, 256>>>(spike_o);
    kC<<<dim3(POST_ / 128, PRE_ / 128), 256>>>(x, W, tpre, tpost, dw_o);
}